// round 1
// baseline (speedup 1.0000x reference)
#include <cuda_runtime.h>
#include <math.h>

#define NNODES 100000
#define HDIM 64

// Scratch (no allocations allowed): per-node accumulator (x,y,z,count) and
// padded positions for 1-sector gathers.
__device__ float4 g_agg[NNODES];
__device__ float4 g_xpad[NNODES];
// Piecewise-linear table for the edge MLP: sorted breakpoints + per-region (A,B)
__device__ float g_ts[HDIM];
__device__ float g_A[HDIM + 1];
__device__ float g_B[HDIM + 1];

// ---------------------------------------------------------------------------
// Build the exact piecewise-linear representation of
//   f(r) = sum_h Wp2[h] * leaky_relu(Wp1[h]*r + bp1[h], 0.2)
// f is linear between breakpoints t_h = -bp1[h]/Wp1[h]; we sort breakpoints and
// evaluate each region at its midpoint to pick the correct slope per unit.
// Units whose breakpoint equals a query r contribute exactly 0 there, so
// boundary assignment is irrelevant — the table is exact.
// ---------------------------------------------------------------------------
__global__ void build_table_kernel(const float* __restrict__ Wp1,
                                   const float* __restrict__ bp1,
                                   const float* __restrict__ Wp2) {
    __shared__ float s_a[HDIM], s_b[HDIM], s_w[HDIM], s_t[HDIM], s_ts[HDIM];
    int h = threadIdx.x;
    if (h < HDIM) {
        float a = Wp1[h], b = bp1[h], w = Wp2[h];
        s_a[h] = a; s_b[h] = b; s_w[h] = w;
        s_t[h] = (a != 0.0f) ? (-b / a) : -1e30f;  // a==0: constant sign, sort first
    }
    __syncthreads();
    if (h < HDIM) {
        // stable rank -> sorted breakpoints
        float t = s_t[h];
        int rank = 0;
        for (int j = 0; j < HDIM; j++) {
            float tj = s_t[j];
            if (tj < t || (tj == t && j < h)) rank++;
        }
        s_ts[rank] = t;
    }
    __syncthreads();
    if (h <= HDIM) {
        float lo = (h == 0)    ? s_ts[0] - 1.0f        : s_ts[h - 1];
        float hi = (h == HDIM) ? s_ts[HDIM - 1] + 1.0f : s_ts[h];
        float rm = 0.5f * (lo + hi);
        float A = 0.0f, B = 0.0f;
        for (int j = 0; j < HDIM; j++) {
            float z = s_a[j] * rm + s_b[j];
            float s = (z >= 0.0f) ? 1.0f : 0.2f;
            A += s_w[j] * s_a[j] * s;
            B += s_w[j] * s_b[j] * s;
        }
        g_A[h] = A;
        g_B[h] = B;
        if (h < HDIM) g_ts[h] = s_ts[h];
    }
}

// Pack x into float4 (single-sector gathers) and zero accumulators.
__global__ void pack_zero_kernel(const float* __restrict__ x, int n) {
    int i = blockIdx.x * blockDim.x + threadIdx.x;
    if (i < n) {
        g_xpad[i] = make_float4(x[3 * i + 0], x[3 * i + 1], x[3 * i + 2], 0.0f);
        g_agg[i]  = make_float4(0.0f, 0.0f, 0.0f, 0.0f);
    }
}

// ---------------------------------------------------------------------------
// Edge phase: gather endpoints, radial distance, table-lookup MLP, tanh,
// atomically scatter m_ij and the edge count into g_agg[row].
// ---------------------------------------------------------------------------
__global__ void edge_kernel(const int* __restrict__ rowp,
                            const int* __restrict__ colp, int E) {
    __shared__ float s_t[HDIM];
    __shared__ float s_A[HDIM + 1];
    __shared__ float s_B[HDIM + 1];
    for (int i = threadIdx.x; i < HDIM; i += blockDim.x) s_t[i] = g_ts[i];
    for (int i = threadIdx.x; i <= HDIM; i += blockDim.x) {
        s_A[i] = g_A[i];
        s_B[i] = g_B[i];
    }
    __syncthreads();

    int e = blockIdx.x * blockDim.x + threadIdx.x;
    if (e >= E) return;

    int r = rowp[e];
    int c = colp[e];
    float4 xr = g_xpad[r];
    float4 xc = g_xpad[c];
    float dx = xr.x - xc.x;
    float dy = xr.y - xc.y;
    float dz = xr.z - xc.z;
    float rad = sqrtf(fmaf(dx, dx, fmaf(dy, dy, dz * dz)));

    // k = #{t_i < rad}  (6 shared-memory probes)
    int lo = 0, hi = HDIM;
    while (lo < hi) {
        int mid = (lo + hi) >> 1;
        if (s_t[mid] < rad) lo = mid + 1; else hi = mid;
    }
    float f  = fmaf(s_A[lo], rad, s_B[lo]);
    float eo = tanhf(f);

    float* ag = reinterpret_cast<float*>(&g_agg[r]);
    atomicAdd(ag + 0, dx * eo);
    atomicAdd(ag + 1, dy * eo);
    atomicAdd(ag + 2, dz * eo);
    atomicAdd(ag + 3, 1.0f);
}

// ---------------------------------------------------------------------------
// Node phase: out = x + agg/max(cnt,1) + vel * coord_mlp_vel(vel_norm)
// ---------------------------------------------------------------------------
__global__ void node_kernel(const float* __restrict__ x,
                            const float* __restrict__ vel,
                            const float* __restrict__ vel_norm,
                            const float* __restrict__ W1,
                            const float* __restrict__ b1,
                            const float* __restrict__ W2,
                            const float* __restrict__ b2,
                            float* __restrict__ out, int n) {
    __shared__ float sW1[HDIM], sb1[HDIM], sW2[HDIM];
    for (int i = threadIdx.x; i < HDIM; i += blockDim.x) {
        sW1[i] = W1[i];
        sb1[i] = b1[i];
        sW2[i] = W2[i];
    }
    __syncthreads();

    int i = blockIdx.x * blockDim.x + threadIdx.x;
    if (i >= n) return;

    float vn = vel_norm[i];
    float acc = b2[0];
#pragma unroll
    for (int h = 0; h < HDIM; h++) {
        float z = fmaf(vn, sW1[h], sb1[h]);
        z = (z >= 0.0f) ? z : 0.2f * z;
        acc = fmaf(z, sW2[h], acc);
    }

    float4 ag = g_agg[i];
    float invc = 1.0f / fmaxf(ag.w, 1.0f);
    out[3 * i + 0] = x[3 * i + 0] + ag.x * invc + vel[3 * i + 0] * acc;
    out[3 * i + 1] = x[3 * i + 1] + ag.y * invc + vel[3 * i + 1] * acc;
    out[3 * i + 2] = x[3 * i + 2] + ag.z * invc + vel[3 * i + 2] * acc;
}

extern "C" void kernel_launch(void* const* d_in, const int* in_sizes, int n_in,
                              void* d_out, int out_size) {
    const float* x        = (const float*)d_in[0];
    const float* vel_norm = (const float*)d_in[1];
    const float* vel      = (const float*)d_in[2];
    const int*   eidx     = (const int*)  d_in[3];
    const float* W1       = (const float*)d_in[4];
    const float* b1       = (const float*)d_in[5];
    const float* W2       = (const float*)d_in[6];
    const float* b2       = (const float*)d_in[7];
    const float* Wp1      = (const float*)d_in[8];
    const float* bp1      = (const float*)d_in[9];
    const float* Wp2      = (const float*)d_in[10];
    float* out = (float*)d_out;

    int n = in_sizes[1];          // number of nodes (vel_norm is [N,1])
    int E = in_sizes[3] / 2;      // edge_index is [2,E]
    const int* rowp = eidx;
    const int* colp = eidx + E;

    build_table_kernel<<<1, 128>>>(Wp1, bp1, Wp2);
    pack_zero_kernel<<<(n + 255) / 256, 256>>>(x, n);
    edge_kernel<<<(E + 255) / 256, 256>>>(rowp, colp, E);
    node_kernel<<<(n + 255) / 256, 256>>>(x, vel, vel_norm, W1, b1, W2, b2, out, n);
}

// round 2
// speedup vs baseline: 1.8301x; 1.8301x over previous
#include <cuda_runtime.h>
#include <math.h>

#define NNODES 100000
#define HDIM 64

__device__ float4 g_agg[NNODES];
__device__ float4 g_xpad[NNODES];
__device__ float g_ts[HDIM];
__device__ float g_A[HDIM + 1];
__device__ float g_B[HDIM + 1];

__device__ __forceinline__ float sqrt_approx(float x) {
    float r;
    asm("sqrt.approx.f32 %0, %1;" : "=f"(r) : "f"(x));
    return r;
}
__device__ __forceinline__ float tanh_approx(float x) {
    float r;
    asm("tanh.approx.f32 %0, %1;" : "=f"(r) : "f"(x));
    return r;
}
__device__ __forceinline__ void red_add_v4(float4* addr, float x, float y,
                                           float z, float w) {
    asm volatile("red.global.add.v4.f32 [%0], {%1, %2, %3, %4};"
                 :: "l"(addr), "f"(x), "f"(y), "f"(z), "f"(w)
                 : "memory");
}

// ---------------------------------------------------------------------------
// Exact piecewise-linear representation of
//   f(r) = sum_h Wp2[h] * leaky_relu(Wp1[h]*r + bp1[h], 0.2)
// ---------------------------------------------------------------------------
__global__ void build_table_kernel(const float* __restrict__ Wp1,
                                   const float* __restrict__ bp1,
                                   const float* __restrict__ Wp2) {
    __shared__ float s_a[HDIM], s_b[HDIM], s_w[HDIM], s_t[HDIM], s_ts[HDIM];
    int h = threadIdx.x;
    if (h < HDIM) {
        float a = Wp1[h], b = bp1[h], w = Wp2[h];
        s_a[h] = a; s_b[h] = b; s_w[h] = w;
        s_t[h] = (a != 0.0f) ? (-b / a) : -1e30f;
    }
    __syncthreads();
    if (h < HDIM) {
        float t = s_t[h];
        int rank = 0;
        for (int j = 0; j < HDIM; j++) {
            float tj = s_t[j];
            if (tj < t || (tj == t && j < h)) rank++;
        }
        s_ts[rank] = t;
    }
    __syncthreads();
    if (h <= HDIM) {
        float lo = (h == 0)    ? s_ts[0] - 1.0f        : s_ts[h - 1];
        float hi = (h == HDIM) ? s_ts[HDIM - 1] + 1.0f : s_ts[h];
        float rm = 0.5f * (lo + hi);
        float A = 0.0f, B = 0.0f;
        for (int j = 0; j < HDIM; j++) {
            float z = s_a[j] * rm + s_b[j];
            float s = (z >= 0.0f) ? 1.0f : 0.2f;
            A += s_w[j] * s_a[j] * s;
            B += s_w[j] * s_b[j] * s;
        }
        g_A[h] = A;
        g_B[h] = B;
        if (h < HDIM) g_ts[h] = s_ts[h];
    }
}

__global__ void pack_zero_kernel(const float* __restrict__ x, int n) {
    int i = blockIdx.x * blockDim.x + threadIdx.x;
    if (i < n) {
        g_xpad[i] = make_float4(x[3 * i + 0], x[3 * i + 1], x[3 * i + 2], 0.0f);
        g_agg[i]  = make_float4(0.0f, 0.0f, 0.0f, 0.0f);
    }
}

// ---------------------------------------------------------------------------
// Edge phase: gather endpoints, radial, PWL table + tanh, one v4 reduction.
// ---------------------------------------------------------------------------
__global__ void __launch_bounds__(256) edge_kernel(const int* __restrict__ rowp,
                                                   const int* __restrict__ colp,
                                                   int E) {
    __shared__ float s_t[HDIM];
    __shared__ float s_A[HDIM + 1];
    __shared__ float s_B[HDIM + 1];
    for (int i = threadIdx.x; i < HDIM; i += blockDim.x) s_t[i] = g_ts[i];
    for (int i = threadIdx.x; i <= HDIM; i += blockDim.x) {
        s_A[i] = g_A[i];
        s_B[i] = g_B[i];
    }
    __syncthreads();

    int e = blockIdx.x * blockDim.x + threadIdx.x;
    if (e >= E) return;

    int r = rowp[e];
    int c = colp[e];
    float4 xr = g_xpad[r];
    float4 xc = g_xpad[c];
    float dx = xr.x - xc.x;
    float dy = xr.y - xc.y;
    float dz = xr.z - xc.z;
    float rr = fmaf(dx, dx, fmaf(dy, dy, dz * dz));
    float rad = sqrt_approx(rr);   // sqrt.approx(0) == 0, safe for self-edges

    int lo = 0, hi = HDIM;
    while (lo < hi) {
        int mid = (lo + hi) >> 1;
        if (s_t[mid] < rad) lo = mid + 1; else hi = mid;
    }
    float f  = fmaf(s_A[lo], rad, s_B[lo]);
    float eo = tanh_approx(f);

    red_add_v4(&g_agg[r], dx * eo, dy * eo, dz * eo, 1.0f);
}

// ---------------------------------------------------------------------------
// Node phase
// ---------------------------------------------------------------------------
__global__ void node_kernel(const float* __restrict__ x,
                            const float* __restrict__ vel,
                            const float* __restrict__ vel_norm,
                            const float* __restrict__ W1,
                            const float* __restrict__ b1,
                            const float* __restrict__ W2,
                            const float* __restrict__ b2,
                            float* __restrict__ out, int n) {
    __shared__ float sW1[HDIM], sb1[HDIM], sW2[HDIM];
    for (int i = threadIdx.x; i < HDIM; i += blockDim.x) {
        sW1[i] = W1[i];
        sb1[i] = b1[i];
        sW2[i] = W2[i];
    }
    __syncthreads();

    int i = blockIdx.x * blockDim.x + threadIdx.x;
    if (i >= n) return;

    float vn = vel_norm[i];
    float acc = b2[0];
#pragma unroll
    for (int h = 0; h < HDIM; h++) {
        float z = fmaf(vn, sW1[h], sb1[h]);
        z = (z >= 0.0f) ? z : 0.2f * z;
        acc = fmaf(z, sW2[h], acc);
    }

    float4 ag = g_agg[i];
    float invc = 1.0f / fmaxf(ag.w, 1.0f);
    out[3 * i + 0] = x[3 * i + 0] + ag.x * invc + vel[3 * i + 0] * acc;
    out[3 * i + 1] = x[3 * i + 1] + ag.y * invc + vel[3 * i + 1] * acc;
    out[3 * i + 2] = x[3 * i + 2] + ag.z * invc + vel[3 * i + 2] * acc;
}

extern "C" void kernel_launch(void* const* d_in, const int* in_sizes, int n_in,
                              void* d_out, int out_size) {
    const float* x        = (const float*)d_in[0];
    const float* vel_norm = (const float*)d_in[1];
    const float* vel      = (const float*)d_in[2];
    const int*   eidx     = (const int*)  d_in[3];
    const float* W1       = (const float*)d_in[4];
    const float* b1       = (const float*)d_in[5];
    const float* W2       = (const float*)d_in[6];
    const float* b2       = (const float*)d_in[7];
    const float* Wp1      = (const float*)d_in[8];
    const float* bp1      = (const float*)d_in[9];
    const float* Wp2      = (const float*)d_in[10];
    float* out = (float*)d_out;

    int n = in_sizes[1];
    int E = in_sizes[3] / 2;
    const int* rowp = eidx;
    const int* colp = eidx + E;

    build_table_kernel<<<1, 128>>>(Wp1, bp1, Wp2);
    pack_zero_kernel<<<(n + 255) / 256, 256>>>(x, n);
    edge_kernel<<<(E + 255) / 256, 256>>>(rowp, colp, E);
    node_kernel<<<(n + 255) / 256, 256>>>(x, vel, vel_norm, W1, b1, W2, b2, out, n);
}

// round 3
// speedup vs baseline: 1.8738x; 1.0239x over previous
#include <cuda_runtime.h>
#include <math.h>

#define NNODES 100000
#define HDIM 64

__device__ float4 g_agg[NNODES];
__device__ float4 g_xpad[NNODES];
// table 0: edge MLP (Wp1,bp1,Wp2, no bias2); table 1: vel MLP (W1,b1,W2,b2)
__device__ float g_ts[2][HDIM];
__device__ float g_A[2][HDIM + 1];
__device__ float g_B[2][HDIM + 1];

__device__ __forceinline__ float sqrt_approx(float x) {
    float r;
    asm("sqrt.approx.f32 %0, %1;" : "=f"(r) : "f"(x));
    return r;
}
__device__ __forceinline__ float tanh_approx(float x) {
    float r;
    asm("tanh.approx.f32 %0, %1;" : "=f"(r) : "f"(x));
    return r;
}
__device__ __forceinline__ void red_add_v4(float4* addr, float x, float y,
                                           float z, float w) {
    asm volatile("red.global.add.v4.f32 [%0], {%1, %2, %3, %4};"
                 :: "l"(addr), "f"(x), "f"(y), "f"(z), "f"(w)
                 : "memory");
}

// ---------------------------------------------------------------------------
// Exact piecewise-linear representation of
//   f(v) = bias2 + sum_h W2[h] * leaky_relu(W1[h]*v + b1[h], 0.2)
// Sorted breakpoints t_h = -b1[h]/W1[h]; per-region slope/intercept (A,B).
// Units at their breakpoint contribute exactly 0 there -> table exact.
// ---------------------------------------------------------------------------
__global__ void build_table_kernel(const float* __restrict__ W1p,
                                   const float* __restrict__ b1p,
                                   const float* __restrict__ W2p,
                                   const float* __restrict__ b2p,  // may be null
                                   int which) {
    __shared__ float s_a[HDIM], s_b[HDIM], s_w[HDIM], s_t[HDIM], s_ts[HDIM];
    int h = threadIdx.x;
    if (h < HDIM) {
        float a = W1p[h], b = b1p[h], w = W2p[h];
        s_a[h] = a; s_b[h] = b; s_w[h] = w;
        s_t[h] = (a != 0.0f) ? (-b / a) : -1e30f;
    }
    __syncthreads();
    if (h < HDIM) {
        float t = s_t[h];
        int rank = 0;
        for (int j = 0; j < HDIM; j++) {
            float tj = s_t[j];
            if (tj < t || (tj == t && j < h)) rank++;
        }
        s_ts[rank] = t;
    }
    __syncthreads();
    if (h <= HDIM) {
        float lo = (h == 0)    ? s_ts[0] - 1.0f        : s_ts[h - 1];
        float hi = (h == HDIM) ? s_ts[HDIM - 1] + 1.0f : s_ts[h];
        float rm = 0.5f * (lo + hi);
        float A = 0.0f, B = (b2p != nullptr) ? b2p[0] : 0.0f;
        for (int j = 0; j < HDIM; j++) {
            float z = s_a[j] * rm + s_b[j];
            float s = (z >= 0.0f) ? 1.0f : 0.2f;
            A += s_w[j] * s_a[j] * s;
            B += s_w[j] * s_b[j] * s;
        }
        g_A[which][h] = A;
        g_B[which][h] = B;
        if (h < HDIM) g_ts[which][h] = s_ts[h];
    }
}

__global__ void pack_zero_kernel(const float* __restrict__ x, int n) {
    int i = blockIdx.x * blockDim.x + threadIdx.x;
    if (i < n) {
        g_xpad[i] = make_float4(x[3 * i + 0], x[3 * i + 1], x[3 * i + 2], 0.0f);
        g_agg[i]  = make_float4(0.0f, 0.0f, 0.0f, 0.0f);
    }
}

__device__ __forceinline__ int pwl_region(const float* s_t, float v) {
    int lo = 0, hi = HDIM;
#pragma unroll
    for (int s = 0; s < 6; s++) {   // 2^6 = 64
        int mid = (lo + hi) >> 1;
        if (s_t[mid] < v) lo = mid + 1; else hi = mid;
    }
    return lo;
}

// ---------------------------------------------------------------------------
// Edge phase: 4 edges/thread, int4 index loads, 8 independent gathers in
// flight, PWL + tanh, one v4 reduction per edge.
// ---------------------------------------------------------------------------
__global__ void __launch_bounds__(256) edge_kernel(const int* __restrict__ rowp,
                                                   const int* __restrict__ colp,
                                                   int E) {
    __shared__ float s_t[HDIM];
    __shared__ float s_A[HDIM + 1];
    __shared__ float s_B[HDIM + 1];
    for (int i = threadIdx.x; i < HDIM; i += blockDim.x) s_t[i] = g_ts[0][i];
    for (int i = threadIdx.x; i <= HDIM; i += blockDim.x) {
        s_A[i] = g_A[0][i];
        s_B[i] = g_B[0][i];
    }
    __syncthreads();

    int t = blockIdx.x * blockDim.x + threadIdx.x;
    int e0 = t * 4;
    if (e0 + 3 < E) {
        int4 r4 = *reinterpret_cast<const int4*>(rowp + e0);
        int4 c4 = *reinterpret_cast<const int4*>(colp + e0);
        float4 xr0 = g_xpad[r4.x];
        float4 xr1 = g_xpad[r4.y];
        float4 xr2 = g_xpad[r4.z];
        float4 xr3 = g_xpad[r4.w];
        float4 xc0 = g_xpad[c4.x];
        float4 xc1 = g_xpad[c4.y];
        float4 xc2 = g_xpad[c4.z];
        float4 xc3 = g_xpad[c4.w];

        float dx0 = xr0.x - xc0.x, dy0 = xr0.y - xc0.y, dz0 = xr0.z - xc0.z;
        float dx1 = xr1.x - xc1.x, dy1 = xr1.y - xc1.y, dz1 = xr1.z - xc1.z;
        float dx2 = xr2.x - xc2.x, dy2 = xr2.y - xc2.y, dz2 = xr2.z - xc2.z;
        float dx3 = xr3.x - xc3.x, dy3 = xr3.y - xc3.y, dz3 = xr3.z - xc3.z;

        float rad0 = sqrt_approx(fmaf(dx0, dx0, fmaf(dy0, dy0, dz0 * dz0)));
        float rad1 = sqrt_approx(fmaf(dx1, dx1, fmaf(dy1, dy1, dz1 * dz1)));
        float rad2 = sqrt_approx(fmaf(dx2, dx2, fmaf(dy2, dy2, dz2 * dz2)));
        float rad3 = sqrt_approx(fmaf(dx3, dx3, fmaf(dy3, dy3, dz3 * dz3)));

        int k0 = pwl_region(s_t, rad0);
        int k1 = pwl_region(s_t, rad1);
        int k2 = pwl_region(s_t, rad2);
        int k3 = pwl_region(s_t, rad3);

        float eo0 = tanh_approx(fmaf(s_A[k0], rad0, s_B[k0]));
        float eo1 = tanh_approx(fmaf(s_A[k1], rad1, s_B[k1]));
        float eo2 = tanh_approx(fmaf(s_A[k2], rad2, s_B[k2]));
        float eo3 = tanh_approx(fmaf(s_A[k3], rad3, s_B[k3]));

        red_add_v4(&g_agg[r4.x], dx0 * eo0, dy0 * eo0, dz0 * eo0, 1.0f);
        red_add_v4(&g_agg[r4.y], dx1 * eo1, dy1 * eo1, dz1 * eo1, 1.0f);
        red_add_v4(&g_agg[r4.z], dx2 * eo2, dy2 * eo2, dz2 * eo2, 1.0f);
        red_add_v4(&g_agg[r4.w], dx3 * eo3, dy3 * eo3, dz3 * eo3, 1.0f);
    } else {
        for (int e = e0; e < E; e++) {
            int r = rowp[e];
            int c = colp[e];
            float4 xr = g_xpad[r];
            float4 xc = g_xpad[c];
            float dx = xr.x - xc.x, dy = xr.y - xc.y, dz = xr.z - xc.z;
            float rad = sqrt_approx(fmaf(dx, dx, fmaf(dy, dy, dz * dz)));
            int k = pwl_region(s_t, rad);
            float eo = tanh_approx(fmaf(s_A[k], rad, s_B[k]));
            red_add_v4(&g_agg[r], dx * eo, dy * eo, dz * eo, 1.0f);
        }
    }
}

// ---------------------------------------------------------------------------
// Node phase: scale(vel_norm) via PWL table (no 64-FMA chain).
// ---------------------------------------------------------------------------
__global__ void node_kernel(const float* __restrict__ vel,
                            const float* __restrict__ vel_norm,
                            float* __restrict__ out, int n) {
    __shared__ float s_t[HDIM];
    __shared__ float s_A[HDIM + 1];
    __shared__ float s_B[HDIM + 1];
    for (int i = threadIdx.x; i < HDIM; i += blockDim.x) s_t[i] = g_ts[1][i];
    for (int i = threadIdx.x; i <= HDIM; i += blockDim.x) {
        s_A[i] = g_A[1][i];
        s_B[i] = g_B[1][i];
    }
    __syncthreads();

    int i = blockIdx.x * blockDim.x + threadIdx.x;
    if (i >= n) return;

    float vn = vel_norm[i];
    int k = pwl_region(s_t, vn);
    float scale = fmaf(s_A[k], vn, s_B[k]);

    float4 xp = g_xpad[i];
    float4 ag = g_agg[i];
    float invc = 1.0f / fmaxf(ag.w, 1.0f);
    out[3 * i + 0] = xp.x + ag.x * invc + vel[3 * i + 0] * scale;
    out[3 * i + 1] = xp.y + ag.y * invc + vel[3 * i + 1] * scale;
    out[3 * i + 2] = xp.z + ag.z * invc + vel[3 * i + 2] * scale;
}

extern "C" void kernel_launch(void* const* d_in, const int* in_sizes, int n_in,
                              void* d_out, int out_size) {
    const float* x        = (const float*)d_in[0];
    const float* vel_norm = (const float*)d_in[1];
    const float* vel      = (const float*)d_in[2];
    const int*   eidx     = (const int*)  d_in[3];
    const float* W1       = (const float*)d_in[4];
    const float* b1       = (const float*)d_in[5];
    const float* W2       = (const float*)d_in[6];
    const float* b2       = (const float*)d_in[7];
    const float* Wp1      = (const float*)d_in[8];
    const float* bp1      = (const float*)d_in[9];
    const float* Wp2      = (const float*)d_in[10];
    float* out = (float*)d_out;

    int n = in_sizes[1];
    int E = in_sizes[3] / 2;
    const int* rowp = eidx;
    const int* colp = eidx + E;

    build_table_kernel<<<1, 128>>>(Wp1, bp1, Wp2, nullptr, 0);
    build_table_kernel<<<1, 128>>>(W1, b1, W2, b2, 1);
    pack_zero_kernel<<<(n + 255) / 256, 256>>>(x, n);
    int nthread = (E + 3) / 4;
    edge_kernel<<<(nthread + 255) / 256, 256>>>(rowp, colp, E);
    node_kernel<<<(n + 255) / 256, 256>>>(vel, vel_norm, out, n);
}

// round 4
// speedup vs baseline: 1.8896x; 1.0084x over previous
#include <cuda_runtime.h>
#include <math.h>

#define NNODES 100000
#define HDIM 64

__device__ float4 g_agg[NNODES];
__device__ float4 g_xpad[NNODES];
// table 0: edge MLP (Wp1,bp1,Wp2, no bias2); table 1: vel MLP (W1,b1,W2,b2)
__device__ float g_ts[2][HDIM];
__device__ float g_A[2][HDIM + 1];
__device__ float g_B[2][HDIM + 1];

__device__ __forceinline__ float sqrt_approx(float x) {
    float r;
    asm("sqrt.approx.f32 %0, %1;" : "=f"(r) : "f"(x));
    return r;
}
__device__ __forceinline__ float tanh_approx(float x) {
    float r;
    asm("tanh.approx.f32 %0, %1;" : "=f"(r) : "f"(x));
    return r;
}
__device__ __forceinline__ void red_add_v4(float4* addr, float x, float y,
                                           float z, float w) {
    asm volatile("red.global.add.v4.f32 [%0], {%1, %2, %3, %4};"
                 :: "l"(addr), "f"(x), "f"(y), "f"(z), "f"(w)
                 : "memory");
}

// ---------------------------------------------------------------------------
// Exact piecewise-linear representation of
//   f(v) = bias2 + sum_h W2[h] * leaky_relu(W1[h]*v + b1[h], 0.2)
// One launch, 2 blocks: block 0 -> edge MLP table, block 1 -> vel MLP table.
// ---------------------------------------------------------------------------
__global__ void build_tables_kernel(const float* __restrict__ Wp1,
                                    const float* __restrict__ bp1,
                                    const float* __restrict__ Wp2,
                                    const float* __restrict__ W1,
                                    const float* __restrict__ b1,
                                    const float* __restrict__ W2,
                                    const float* __restrict__ b2) {
    __shared__ float s_a[HDIM], s_b[HDIM], s_w[HDIM], s_t[HDIM], s_ts[HDIM];
    int which = blockIdx.x;
    const float* W1p = (which == 0) ? Wp1 : W1;
    const float* b1p = (which == 0) ? bp1 : b1;
    const float* W2p = (which == 0) ? Wp2 : W2;
    float bias2 = 0.0f;

    int h = threadIdx.x;
    if (h < HDIM) {
        float a = W1p[h], b = b1p[h], w = W2p[h];
        s_a[h] = a; s_b[h] = b; s_w[h] = w;
        s_t[h] = (a != 0.0f) ? (-b / a) : -1e30f;
    }
    if (which == 1) bias2 = b2[0];
    __syncthreads();
    if (h < HDIM) {
        float t = s_t[h];
        int rank = 0;
        for (int j = 0; j < HDIM; j++) {
            float tj = s_t[j];
            if (tj < t || (tj == t && j < h)) rank++;
        }
        s_ts[rank] = t;
    }
    __syncthreads();
    if (h <= HDIM) {
        float lo = (h == 0)    ? s_ts[0] - 1.0f        : s_ts[h - 1];
        float hi = (h == HDIM) ? s_ts[HDIM - 1] + 1.0f : s_ts[h];
        float rm = 0.5f * (lo + hi);
        float A = 0.0f, B = bias2;
        for (int j = 0; j < HDIM; j++) {
            float z = s_a[j] * rm + s_b[j];
            float s = (z >= 0.0f) ? 1.0f : 0.2f;
            A += s_w[j] * s_a[j] * s;
            B += s_w[j] * s_b[j] * s;
        }
        g_A[which][h] = A;
        g_B[which][h] = B;
        if (h < HDIM) g_ts[which][h] = s_ts[h];
    }
}

__global__ void pack_zero_kernel(const float* __restrict__ x, int n) {
    int i = blockIdx.x * blockDim.x + threadIdx.x;
    if (i < n) {
        g_xpad[i] = make_float4(x[3 * i + 0], x[3 * i + 1], x[3 * i + 2], 0.0f);
        g_agg[i]  = make_float4(0.0f, 0.0f, 0.0f, 0.0f);
    }
}

__device__ __forceinline__ int pwl_region(const float* s_t, float v) {
    int lo = 0, hi = HDIM;
#pragma unroll
    for (int s = 0; s < 6; s++) {   // 2^6 = 64
        int mid = (lo + hi) >> 1;
        if (s_t[mid] < v) lo = mid + 1; else hi = mid;
    }
    return lo;
}

// ---------------------------------------------------------------------------
// Edge phase: 2 edges/thread (low reg pressure -> high occupancy), streamed
// index loads bypass L1 retention, 4 independent gathers in flight.
// ---------------------------------------------------------------------------
__global__ void __launch_bounds__(256) edge_kernel(const int* __restrict__ rowp,
                                                   const int* __restrict__ colp,
                                                   int E) {
    __shared__ float s_t[HDIM];
    __shared__ float s_A[HDIM + 1];
    __shared__ float s_B[HDIM + 1];
    for (int i = threadIdx.x; i < HDIM; i += blockDim.x) s_t[i] = g_ts[0][i];
    for (int i = threadIdx.x; i <= HDIM; i += blockDim.x) {
        s_A[i] = g_A[0][i];
        s_B[i] = g_B[0][i];
    }
    __syncthreads();

    int t = blockIdx.x * blockDim.x + threadIdx.x;
    int e0 = t * 2;
    if (e0 + 1 < E) {
        int2 r2 = __ldcs(reinterpret_cast<const int2*>(rowp + e0));
        int2 c2 = __ldcs(reinterpret_cast<const int2*>(colp + e0));

        float4 xr0 = g_xpad[r2.x];
        float4 xr1 = g_xpad[r2.y];
        float4 xc0 = g_xpad[c2.x];
        float4 xc1 = g_xpad[c2.y];

        float dx0 = xr0.x - xc0.x, dy0 = xr0.y - xc0.y, dz0 = xr0.z - xc0.z;
        float dx1 = xr1.x - xc1.x, dy1 = xr1.y - xc1.y, dz1 = xr1.z - xc1.z;

        float rad0 = sqrt_approx(fmaf(dx0, dx0, fmaf(dy0, dy0, dz0 * dz0)));
        float rad1 = sqrt_approx(fmaf(dx1, dx1, fmaf(dy1, dy1, dz1 * dz1)));

        int k0 = pwl_region(s_t, rad0);
        int k1 = pwl_region(s_t, rad1);

        float eo0 = tanh_approx(fmaf(s_A[k0], rad0, s_B[k0]));
        float eo1 = tanh_approx(fmaf(s_A[k1], rad1, s_B[k1]));

        red_add_v4(&g_agg[r2.x], dx0 * eo0, dy0 * eo0, dz0 * eo0, 1.0f);
        red_add_v4(&g_agg[r2.y], dx1 * eo1, dy1 * eo1, dz1 * eo1, 1.0f);
    } else {
        for (int e = e0; e < E; e++) {
            int r = rowp[e];
            int c = colp[e];
            float4 xr = g_xpad[r];
            float4 xc = g_xpad[c];
            float dx = xr.x - xc.x, dy = xr.y - xc.y, dz = xr.z - xc.z;
            float rad = sqrt_approx(fmaf(dx, dx, fmaf(dy, dy, dz * dz)));
            int k = pwl_region(s_t, rad);
            float eo = tanh_approx(fmaf(s_A[k], rad, s_B[k]));
            red_add_v4(&g_agg[r], dx * eo, dy * eo, dz * eo, 1.0f);
        }
    }
}

// ---------------------------------------------------------------------------
// Node phase: scale(vel_norm) via PWL table.
// ---------------------------------------------------------------------------
__global__ void node_kernel(const float* __restrict__ vel,
                            const float* __restrict__ vel_norm,
                            float* __restrict__ out, int n) {
    __shared__ float s_t[HDIM];
    __shared__ float s_A[HDIM + 1];
    __shared__ float s_B[HDIM + 1];
    for (int i = threadIdx.x; i < HDIM; i += blockDim.x) s_t[i] = g_ts[1][i];
    for (int i = threadIdx.x; i <= HDIM; i += blockDim.x) {
        s_A[i] = g_A[1][i];
        s_B[i] = g_B[1][i];
    }
    __syncthreads();

    int i = blockIdx.x * blockDim.x + threadIdx.x;
    if (i >= n) return;

    float vn = vel_norm[i];
    int k = pwl_region(s_t, vn);
    float scale = fmaf(s_A[k], vn, s_B[k]);

    float4 xp = g_xpad[i];
    float4 ag = g_agg[i];
    float invc = 1.0f / fmaxf(ag.w, 1.0f);
    out[3 * i + 0] = xp.x + ag.x * invc + vel[3 * i + 0] * scale;
    out[3 * i + 1] = xp.y + ag.y * invc + vel[3 * i + 1] * scale;
    out[3 * i + 2] = xp.z + ag.z * invc + vel[3 * i + 2] * scale;
}

extern "C" void kernel_launch(void* const* d_in, const int* in_sizes, int n_in,
                              void* d_out, int out_size) {
    const float* x        = (const float*)d_in[0];
    const float* vel_norm = (const float*)d_in[1];
    const float* vel      = (const float*)d_in[2];
    const int*   eidx     = (const int*)  d_in[3];
    const float* W1       = (const float*)d_in[4];
    const float* b1       = (const float*)d_in[5];
    const float* W2       = (const float*)d_in[6];
    const float* b2       = (const float*)d_in[7];
    const float* Wp1      = (const float*)d_in[8];
    const float* bp1      = (const float*)d_in[9];
    const float* Wp2      = (const float*)d_in[10];
    float* out = (float*)d_out;

    int n = in_sizes[1];
    int E = in_sizes[3] / 2;
    const int* rowp = eidx;
    const int* colp = eidx + E;

    build_tables_kernel<<<2, 128>>>(Wp1, bp1, Wp2, W1, b1, W2, b2);
    pack_zero_kernel<<<(n + 255) / 256, 256>>>(x, n);
    int nthread = (E + 1) / 2;
    edge_kernel<<<(nthread + 255) / 256, 256>>>(rowp, colp, E);
    node_kernel<<<(n + 255) / 256, 256>>>(vel, vel_norm, out, n);
}

// round 5
// speedup vs baseline: 1.9196x; 1.0159x over previous
#include <cuda_runtime.h>
#include <math.h>

#define NNODES 100000
#define HDIM 64

__device__ float4 g_agg[NNODES];
__device__ float4 g_xpad[NNODES];
// table 0: edge MLP (Wp1,bp1,Wp2, no bias2); table 1: vel MLP (W1,b1,W2,b2)
__device__ float g_ts[2][HDIM];
__device__ float g_A[2][HDIM + 1];
__device__ float g_B[2][HDIM + 1];

__device__ __forceinline__ float sqrt_approx(float x) {
    float r;
    asm("sqrt.approx.f32 %0, %1;" : "=f"(r) : "f"(x));
    return r;
}
__device__ __forceinline__ float tanh_approx(float x) {
    float r;
    asm("tanh.approx.f32 %0, %1;" : "=f"(r) : "f"(x));
    return r;
}
__device__ __forceinline__ void red_add_v4(float4* addr, float x, float y,
                                           float z, float w) {
    asm volatile("red.global.add.v4.f32 [%0], {%1, %2, %3, %4};"
                 :: "l"(addr), "f"(x), "f"(y), "f"(z), "f"(w)
                 : "memory");
}

__device__ __forceinline__ int pwl_region(const float* s_t, float v) {
    int lo = 0, hi = HDIM;
#pragma unroll
    for (int s = 0; s < 6; s++) {   // 2^6 = 64
        int mid = (lo + hi) >> 1;
        if (s_t[mid] < v) lo = mid + 1; else hi = mid;
    }
    return lo;
}

// ---------------------------------------------------------------------------
// Fused prep: every block packs a slice of x into float4 and zeros g_agg;
// blocks 0 and 1 additionally build the exact piecewise-linear tables for
//   f(v) = bias2 + sum_h W2[h] * leaky_relu(W1[h]*v + b1[h], 0.2)
// (block 0 -> edge MLP, block 1 -> vel MLP).
// ---------------------------------------------------------------------------
__global__ void prep_kernel(const float* __restrict__ x, int n,
                            const float* __restrict__ Wp1,
                            const float* __restrict__ bp1,
                            const float* __restrict__ Wp2,
                            const float* __restrict__ W1,
                            const float* __restrict__ b1,
                            const float* __restrict__ W2,
                            const float* __restrict__ b2) {
    int i = blockIdx.x * blockDim.x + threadIdx.x;
    if (i < n) {
        g_xpad[i] = make_float4(x[3 * i + 0], x[3 * i + 1], x[3 * i + 2], 0.0f);
        g_agg[i]  = make_float4(0.0f, 0.0f, 0.0f, 0.0f);
    }

    if (blockIdx.x < 2) {
        __shared__ float s_a[HDIM], s_b[HDIM], s_w[HDIM], s_t[HDIM], s_ts[HDIM];
        int which = blockIdx.x;
        const float* W1p = (which == 0) ? Wp1 : W1;
        const float* b1p = (which == 0) ? bp1 : b1;
        const float* W2p = (which == 0) ? Wp2 : W2;
        float bias2 = (which == 1) ? b2[0] : 0.0f;

        int h = threadIdx.x;
        if (h < HDIM) {
            float a = W1p[h], b = b1p[h], w = W2p[h];
            s_a[h] = a; s_b[h] = b; s_w[h] = w;
            s_t[h] = (a != 0.0f) ? (-b / a) : -1e30f;
        }
        __syncthreads();
        if (h < HDIM) {
            float t = s_t[h];
            int rank = 0;
            for (int j = 0; j < HDIM; j++) {
                float tj = s_t[j];
                if (tj < t || (tj == t && j < h)) rank++;
            }
            s_ts[rank] = t;
        }
        __syncthreads();
        if (h <= HDIM) {
            float lo = (h == 0)    ? s_ts[0] - 1.0f        : s_ts[h - 1];
            float hi = (h == HDIM) ? s_ts[HDIM - 1] + 1.0f : s_ts[h];
            float rm = 0.5f * (lo + hi);
            float A = 0.0f, B = bias2;
            for (int j = 0; j < HDIM; j++) {
                float z = s_a[j] * rm + s_b[j];
                float s = (z >= 0.0f) ? 1.0f : 0.2f;
                A += s_w[j] * s_a[j] * s;
                B += s_w[j] * s_b[j] * s;
            }
            g_A[which][h] = A;
            g_B[which][h] = B;
            if (h < HDIM) g_ts[which][h] = s_ts[h];
        }
    }
}

// ---------------------------------------------------------------------------
// Edge phase: 2 edges/thread; structurally bound by L1tex wavefronts
// (2 random gathers + 1 red per edge).
// ---------------------------------------------------------------------------
__global__ void __launch_bounds__(256) edge_kernel(const int* __restrict__ rowp,
                                                   const int* __restrict__ colp,
                                                   int E) {
    __shared__ float s_t[HDIM];
    __shared__ float s_A[HDIM + 1];
    __shared__ float s_B[HDIM + 1];
    for (int i = threadIdx.x; i < HDIM; i += blockDim.x) s_t[i] = g_ts[0][i];
    for (int i = threadIdx.x; i <= HDIM; i += blockDim.x) {
        s_A[i] = g_A[0][i];
        s_B[i] = g_B[0][i];
    }
    __syncthreads();

    int t = blockIdx.x * blockDim.x + threadIdx.x;
    int e0 = t * 2;
    if (e0 + 1 < E) {
        int2 r2 = __ldcs(reinterpret_cast<const int2*>(rowp + e0));
        int2 c2 = __ldcs(reinterpret_cast<const int2*>(colp + e0));

        float4 xr0 = g_xpad[r2.x];
        float4 xr1 = g_xpad[r2.y];
        float4 xc0 = g_xpad[c2.x];
        float4 xc1 = g_xpad[c2.y];

        float dx0 = xr0.x - xc0.x, dy0 = xr0.y - xc0.y, dz0 = xr0.z - xc0.z;
        float dx1 = xr1.x - xc1.x, dy1 = xr1.y - xc1.y, dz1 = xr1.z - xc1.z;

        float rad0 = sqrt_approx(fmaf(dx0, dx0, fmaf(dy0, dy0, dz0 * dz0)));
        float rad1 = sqrt_approx(fmaf(dx1, dx1, fmaf(dy1, dy1, dz1 * dz1)));

        int k0 = pwl_region(s_t, rad0);
        int k1 = pwl_region(s_t, rad1);

        float eo0 = tanh_approx(fmaf(s_A[k0], rad0, s_B[k0]));
        float eo1 = tanh_approx(fmaf(s_A[k1], rad1, s_B[k1]));

        red_add_v4(&g_agg[r2.x], dx0 * eo0, dy0 * eo0, dz0 * eo0, 1.0f);
        red_add_v4(&g_agg[r2.y], dx1 * eo1, dy1 * eo1, dz1 * eo1, 1.0f);
    } else {
        for (int e = e0; e < E; e++) {
            int r = rowp[e];
            int c = colp[e];
            float4 xr = g_xpad[r];
            float4 xc = g_xpad[c];
            float dx = xr.x - xc.x, dy = xr.y - xc.y, dz = xr.z - xc.z;
            float rad = sqrt_approx(fmaf(dx, dx, fmaf(dy, dy, dz * dz)));
            int k = pwl_region(s_t, rad);
            float eo = tanh_approx(fmaf(s_A[k], rad, s_B[k]));
            red_add_v4(&g_agg[r], dx * eo, dy * eo, dz * eo, 1.0f);
        }
    }
}

// ---------------------------------------------------------------------------
// Node phase: issue all global loads BEFORE the table fill + barrier so their
// latency overlaps the barrier (kernel was 9% issue / pure latency).
// ---------------------------------------------------------------------------
__global__ void node_kernel(const float* __restrict__ vel,
                            const float* __restrict__ vel_norm,
                            float* __restrict__ out, int n) {
    __shared__ float s_t[HDIM];
    __shared__ float s_A[HDIM + 1];
    __shared__ float s_B[HDIM + 1];

    int i = blockIdx.x * blockDim.x + threadIdx.x;
    bool active = (i < n);

    // Early global loads (independent of shared memory)
    float vn = 0.0f;
    float4 xp = make_float4(0, 0, 0, 0);
    float4 ag = make_float4(0, 0, 0, 0);
    float v0 = 0.0f, v1 = 0.0f, v2 = 0.0f;
    if (active) {
        vn = vel_norm[i];
        xp = g_xpad[i];
        ag = g_agg[i];
        v0 = vel[3 * i + 0];
        v1 = vel[3 * i + 1];
        v2 = vel[3 * i + 2];
    }

    for (int j = threadIdx.x; j < HDIM; j += blockDim.x) s_t[j] = g_ts[1][j];
    for (int j = threadIdx.x; j <= HDIM; j += blockDim.x) {
        s_A[j] = g_A[1][j];
        s_B[j] = g_B[1][j];
    }
    __syncthreads();

    if (!active) return;

    int k = pwl_region(s_t, vn);
    float scale = fmaf(s_A[k], vn, s_B[k]);

    float invc = 1.0f / fmaxf(ag.w, 1.0f);
    out[3 * i + 0] = xp.x + ag.x * invc + v0 * scale;
    out[3 * i + 1] = xp.y + ag.y * invc + v1 * scale;
    out[3 * i + 2] = xp.z + ag.z * invc + v2 * scale;
}

extern "C" void kernel_launch(void* const* d_in, const int* in_sizes, int n_in,
                              void* d_out, int out_size) {
    const float* x        = (const float*)d_in[0];
    const float* vel_norm = (const float*)d_in[1];
    const float* vel      = (const float*)d_in[2];
    const int*   eidx     = (const int*)  d_in[3];
    const float* W1       = (const float*)d_in[4];
    const float* b1       = (const float*)d_in[5];
    const float* W2       = (const float*)d_in[6];
    const float* b2       = (const float*)d_in[7];
    const float* Wp1      = (const float*)d_in[8];
    const float* bp1      = (const float*)d_in[9];
    const float* Wp2      = (const float*)d_in[10];
    float* out = (float*)d_out;

    int n = in_sizes[1];
    int E = in_sizes[3] / 2;
    const int* rowp = eidx;
    const int* colp = eidx + E;

    int nblk = (n + 255) / 256;
    if (nblk < 2) nblk = 2;
    prep_kernel<<<nblk, 256>>>(x, n, Wp1, bp1, Wp2, W1, b1, W2, b2);
    int nthread = (E + 1) / 2;
    edge_kernel<<<(nthread + 255) / 256, 256>>>(rowp, colp, E);
    node_kernel<<<(n + 255) / 256, 256>>>(vel, vel_norm, out, n);
}